// round 13
// baseline (speedup 1.0000x reference)
#include <cuda_runtime.h>
#include <cuda_bf16.h>
#include <cstdint>

// Problem constants (fixed-shape problem)
#define Bn 16
#define Nn 10000
#define Tn 24
#define Hn 32
#define On 16
#define Mn (Bn*Nn)          // 160000 rows
#define G3H 96              // 3*H

// ---------------- device scratch (no allocations allowed) ----------------
__device__ float g_h   [Mn*Hn];   // GRU output, layout [n][b][32]
__device__ float g_xw1 [Mn*Hn];   // conv1 x@W1,   [n][b][32]
__device__ float g_out1[Mn*Hn];   // conv1 result, [n][b][32]
__device__ float g_xw2 [Mn*On];   // conv2 x@W2,   [n][b][16]
__device__ float g_out2[Mn*On];   // conv2 result, [n][b][16]
__device__ float g_deg [Nn];
__device__ float g_dinv[Nn];

// ---------------- helpers ----------------
__device__ __forceinline__ float tanhap(float x){
    float y;
    asm("tanh.approx.f32 %0, %1;" : "=f"(y) : "f"(x));
    return y;
}
__device__ __forceinline__ uint32_t pack_bf2(__nv_bfloat16 lo, __nv_bfloat16 hi){
    __nv_bfloat162 t = __halves2bfloat162(lo, hi);   // .x -> low 16 bits
    return *reinterpret_cast<uint32_t*>(&t);
}
// split two floats into packed bf16 hi + residual lo
__device__ __forceinline__ void split2(float a, float b, uint32_t& hi, uint32_t& lo){
    __nv_bfloat16 ah = __float2bfloat16(a), bh = __float2bfloat16(b);
    hi = pack_bf2(ah, bh);
    lo = pack_bf2(__float2bfloat16(a - __bfloat162float(ah)),
                  __float2bfloat16(b - __bfloat162float(bh)));
}
__device__ __forceinline__ void mma_bf16(float* d, const uint32_t* a, uint32_t b0, uint32_t b1){
    asm volatile("mma.sync.aligned.m16n8k16.row.col.f32.bf16.bf16.f32 "
        "{%0,%1,%2,%3}, {%4,%5,%6,%7}, {%8,%9}, {%0,%1,%2,%3};"
        : "+f"(d[0]),"+f"(d[1]),"+f"(d[2]),"+f"(d[3])
        : "r"(a[0]),"r"(a[1]),"r"(a[2]),"r"(a[3]), "r"(b0),"r"(b1));
}

// ---------------- degree / norm ----------------
__global__ void deg_init_kernel(){
    int i = blockIdx.x*blockDim.x + threadIdx.x;
    if (i < Nn) g_deg[i] = 1.f;               // self-loop weight
}
__global__ void deg_acc_kernel(const int* __restrict__ ei,
                               const float* __restrict__ ew, int E){
    int e = blockIdx.x*blockDim.x + threadIdx.x;
    if (e < E) atomicAdd(&g_deg[ei[E + e]], ew[e]);
}
__global__ void dinv_kernel(){
    int i = blockIdx.x*blockDim.x + threadIdx.x;
    if (i < Nn){
        float d = g_deg[i];
        g_dinv[i] = d > 0.f ? rsqrtf(d) : 0.f;
    }
}

// ---------------- GRU via warp-level mma.sync (bf16 hi/lo split) ----------------
// Warp = 16 sequences. Per step: D[16,96] = A[16,32] x B[32,96] via MMA with
// D PRE-INITIALIZED to the exact fp32 x/bias contribution (accumulate-in).
//   A = h(32) bf16 hi/lo; B = w_hh per gate. n-tiles: 0-3 r, 4-7 z, 8-11 nh.
//   xn = win*x + bxn computed scalar (exact), kept in registers.
// h persists in D-layout fragment registers; B frags in smem as ONE uint4 per
// (tile, ktile, lane) -> single LDS.128 per MMA group (was 4x LDS.32).
__device__ __forceinline__ float bval(int nt, int k, int gcol, const float* w_hh){
    int gate = nt >> 2;
    int u = (nt & 3)*8 + gcol;
    return w_hh[(gate*32 + u)*32 + k];
}

__global__ __launch_bounds__(128,3)
void gru_mma_kernel(const float* __restrict__ x,
                    const float* __restrict__ w_ih, const float* __restrict__ w_hh,
                    const float* __restrict__ b_ih, const float* __restrict__ b_hh)
{
    // B fragments: [tile][ktile][lane] = (bh_r0, bh_r1, bl_r0, bl_r1)
    __shared__ uint4 sB4[12][2][32];
    // per-unit gate constants: sc4[2u]=(wir,wiz,win,bR), sc4[2u+1]=(bZ,bhn,bxn,0)
    __shared__ float4 sc4[64];

    const int tid  = threadIdx.x;
    const int lane = tid & 31;
    const int wid  = tid >> 5;
    const int g    = lane >> 2;      // fragment group (row / B n-col)
    const int tig  = lane & 3;       // thread in group

    // ---- one-time B fragment staging (h-part only) ----
    for (int i = tid; i < 12*2*32; i += 128){
        int nt = i >> 6;             // /64
        int kt = (i >> 5) & 1;
        int ln = i & 31;
        int gg = ln >> 2, tg = ln & 3;
        uint32_t h0, l0, h1, l1;
        {   int k0 = 16*kt + 2*tg;
            split2(bval(nt, k0, gg, w_hh), bval(nt, k0+1, gg, w_hh), h0, l0); }
        {   int k0 = 16*kt + 2*tg + 8;
            split2(bval(nt, k0, gg, w_hh), bval(nt, k0+1, gg, w_hh), h1, l1); }
        sB4[nt][kt][ln] = make_uint4(h0, h1, l0, l1);
    }
    // ---- one-time gate-constant staging ----
    if (tid < 64){
        int u = tid >> 1;
        if ((tid & 1) == 0)
            sc4[tid] = make_float4(w_ih[u], w_ih[32+u], w_ih[64+u], b_ih[u] + b_hh[u]);
        else
            sc4[tid] = make_float4(b_ih[32+u] + b_hh[32+u], b_hh[64+u], b_ih[64+u], 0.f);
    }
    __syncthreads();

    const int m0 = blockIdx.x*64 + wid*16;      // 2500 blocks * 4 warps * 16 seqs
    const float* xa = x + (size_t)(m0 + g    )*Tn;
    const float* xb = x + (size_t)(m0 + g + 8)*Tn;

    // h in D-fragment layout: h[nt][e], nt=0..3 (units 8nt+2tig+{0,1}; rows g,g+8)
    float h[4][4];
#pragma unroll
    for (int a = 0; a < 4; a++)
#pragma unroll
        for (int e = 0; e < 4; e++) h[a][e] = 0.f;

#pragma unroll 2
    for (int t = 0; t < Tn; t++){
        // ---- pack A fragments (hi/lo) from h (k = 0..31 only) ----
        uint32_t Ah[2][4], Al[2][4];
#pragma unroll
        for (int kt = 0; kt < 2; kt++){
            split2(h[2*kt  ][0], h[2*kt  ][1], Ah[kt][0], Al[kt][0]);
            split2(h[2*kt  ][2], h[2*kt  ][3], Ah[kt][1], Al[kt][1]);
            split2(h[2*kt+1][0], h[2*kt+1][1], Ah[kt][2], Al[kt][2]);
            split2(h[2*kt+1][2], h[2*kt+1][3], Ah[kt][3], Al[kt][3]);
        }

        // ---- D init: exact fp32 x/bias contribution (broadcast LDS) ----
        float xga = __ldg(xa + t);
        float xgb = __ldg(xb + t);
        float D[12][4], Xn[4][4];
#pragma unroll
        for (int nt = 0; nt < 4; nt++){
#pragma unroll
            for (int eo = 0; eo < 2; eo++){
                int u = 8*nt + 2*tig + eo;
                float4 c0 = sc4[2*u];       // wir,wiz,win,bR
                float4 c1 = sc4[2*u+1];     // bZ,bhn,bxn,-
                D [nt  ][eo  ] = fmaf(c0.x, xga, c0.w);
                D [nt  ][eo+2] = fmaf(c0.x, xgb, c0.w);
                D [nt+4][eo  ] = fmaf(c0.y, xga, c1.x);
                D [nt+4][eo+2] = fmaf(c0.y, xgb, c1.x);
                D [nt+8][eo  ] = c1.y;
                D [nt+8][eo+2] = c1.y;
                Xn[nt  ][eo  ] = fmaf(c0.z, xga, c1.z);
                Xn[nt  ][eo+2] = fmaf(c0.z, xgb, c1.z);
            }
        }

        // ---- MMAs: 12 tiles x 2 k-tiles x 3 split products, accumulate into D ----
#pragma unroll
        for (int nt = 0; nt < 12; nt++){
#pragma unroll
            for (int kt = 0; kt < 2; kt++){
                uint4 bb = sB4[nt][kt][lane];     // one LDS.128
                mma_bf16(D[nt], Ah[kt], bb.x, bb.y);
                mma_bf16(D[nt], Al[kt], bb.x, bb.y);
                mma_bf16(D[nt], Ah[kt], bb.z, bb.w);
            }
        }

        // ---- gates + state update (element-wise, same fragment positions) ----
#pragma unroll
        for (int nt = 0; nt < 4; nt++)
#pragma unroll
            for (int e = 0; e < 4; e++){
                float r  = fmaf(0.5f, tanhap(0.5f*D[nt  ][e]), 0.5f);
                float z  = fmaf(0.5f, tanhap(0.5f*D[nt+4][e]), 0.5f);
                float nv = tanhap(fmaf(r, D[nt+8][e], Xn[nt][e]));
                h[nt][e] = fmaf(z, h[nt][e] - nv, nv);
            }
    }

    // ---- write final h: thread owns (rows g,g+8) x (cols 8nt+2tig,+1) ----
#pragma unroll
    for (int nt = 0; nt < 4; nt++){
        int j0 = nt*8 + 2*tig;
        {
            int m = m0 + g;
            int b = m / Nn, nn = m % Nn;
            *(float2*)(g_h + ((size_t)nn*Bn + b)*Hn + j0) = make_float2(h[nt][0], h[nt][1]);
        }
        {
            int m = m0 + g + 8;
            int b = m / Nn, nn = m % Nn;
            *(float2*)(g_h + ((size_t)nn*Bn + b)*Hn + j0) = make_float2(h[nt][2], h[nt][3]);
        }
    }
}

// ---------------- dense matmul + self-loop init (+ optional bias+relu on input) ----------------
template<int CIN, int COUT, bool RELU>
__global__ void mm_init_kernel(const float* __restrict__ in,
                               const float* __restrict__ W,
                               const float* __restrict__ bin,
                               float* __restrict__ xw,
                               float* __restrict__ outbuf)
{
    __shared__ float sW[CIN*COUT];
    __shared__ float sb[CIN];
    int tid = threadIdx.x;
    for (int i = tid; i < CIN*COUT; i += blockDim.x) sW[i] = W[i];
    if (RELU && tid < CIN) sb[tid] = bin[tid];
    __syncthreads();

    int r = blockIdx.x*blockDim.x + tid;
    if (r >= Mn) return;
    int n = r / Bn;
    float di = g_dinv[n];
    float dd = di*di;                         // self-loop norm

    float v[CIN];
#pragma unroll
    for (int i = 0; i < CIN; i += 4){
        float4 t4 = *(const float4*)(in + (size_t)r*CIN + i);
        v[i]=t4.x; v[i+1]=t4.y; v[i+2]=t4.z; v[i+3]=t4.w;
    }
    if (RELU){
#pragma unroll
        for (int i = 0; i < CIN; i++) v[i] = fmaxf(v[i] + sb[i], 0.f);
    }
    float acc[COUT];
#pragma unroll
    for (int o = 0; o < COUT; o++) acc[o] = 0.f;
#pragma unroll
    for (int i = 0; i < CIN; i++){
        float vi = v[i];
#pragma unroll
        for (int o = 0; o < COUT; o++) acc[o] += vi * sW[i*COUT + o];
    }
    float* px = xw     + (size_t)r*COUT;
    float* po = outbuf + (size_t)r*COUT;
#pragma unroll
    for (int o = 0; o < COUT; o += 4){
        *(float4*)(px+o) = make_float4(acc[o],    acc[o+1],    acc[o+2],    acc[o+3]);
        *(float4*)(po+o) = make_float4(dd*acc[o], dd*acc[o+1], dd*acc[o+2], dd*acc[o+3]);
    }
}

// ---------------- edge scatter: one warp per edge, vectorized fp32 RED ----------------
__device__ __forceinline__ void red4(float* p, float4 v){
    asm volatile("red.global.add.v4.f32 [%0], {%1, %2, %3, %4};"
                 :: "l"(p), "f"(v.x), "f"(v.y), "f"(v.z), "f"(v.w) : "memory");
}

template<int C>
__global__ void scatter_kernel(const int* __restrict__ ei,
                               const float* __restrict__ ew,
                               const float* __restrict__ xw,
                               float* __restrict__ out, int E)
{
    int g    = blockIdx.x*blockDim.x + threadIdx.x;
    int warp = g >> 5;
    int lane = g & 31;
    if (warp >= E) return;

    int src = 0, tgt = 0; float nrm = 0.f;
    if (lane == 0){
        src = ei[warp];
        tgt = ei[E + warp];
        nrm = g_dinv[src] * ew[warp] * g_dinv[tgt];
    }
    src = __shfl_sync(0xffffffffu, src, 0);
    tgt = __shfl_sync(0xffffffffu, tgt, 0);
    nrm = __shfl_sync(0xffffffffu, nrm, 0);

    const float4* s = (const float4*)(xw + (size_t)src*(Bn*C));
    float*        d = out + (size_t)tgt*(Bn*C);
#pragma unroll
    for (int i = 0; i < (Bn*C)/128; i++){
        float4 v = s[lane + 32*i];
        v.x *= nrm; v.y *= nrm; v.z *= nrm; v.w *= nrm;
        red4(d + 4*(lane + 32*i), v);
    }
}

// ---------------- final linear head + [b][n] transpose ----------------
__global__ void final_kernel(const float* __restrict__ b2,
                             const float* __restrict__ Wfc,
                             const float* __restrict__ bfc,
                             float* __restrict__ y)
{
    int r = blockIdx.x*blockDim.x + threadIdx.x;
    if (r >= Mn) return;
    int n = r / Bn, b = r % Bn;
    const float* row = g_out2 + (size_t)r*On;
    float acc = bfc[0];
#pragma unroll
    for (int o = 0; o < On; o++) acc += (row[o] + b2[o]) * Wfc[o];
    y[(size_t)b*Nn + n] = acc;
}

// ---------------- launch ----------------
extern "C" void kernel_launch(void* const* d_in, const int* in_sizes, int n_in,
                              void* d_out, int out_size)
{
    const float* x    = (const float*)d_in[0];
    const int*   ei   = (const int*)  d_in[1];
    const float* ew   = (const float*)d_in[2];
    const float* w_ih = (const float*)d_in[3];
    const float* w_hh = (const float*)d_in[4];
    const float* b_ih = (const float*)d_in[5];
    const float* b_hh = (const float*)d_in[6];
    const float* W1   = (const float*)d_in[7];
    const float* b1   = (const float*)d_in[8];
    const float* W2   = (const float*)d_in[9];
    const float* b2   = (const float*)d_in[10];
    const float* Wfc  = (const float*)d_in[11];
    const float* bfc  = (const float*)d_in[12];
    float* y = (float*)d_out;
    int E = in_sizes[2];

    // resolve __device__ scratch addresses (not an allocation)
    float *p_h, *p_xw1, *p_out1, *p_xw2, *p_out2;
    cudaGetSymbolAddress((void**)&p_h,    g_h);
    cudaGetSymbolAddress((void**)&p_xw1,  g_xw1);
    cudaGetSymbolAddress((void**)&p_out1, g_out1);
    cudaGetSymbolAddress((void**)&p_xw2,  g_xw2);
    cudaGetSymbolAddress((void**)&p_out2, g_out2);

    // 1) gcn_norm
    deg_init_kernel<<<(Nn+255)/256, 256>>>();
    deg_acc_kernel <<<(E +255)/256, 256>>>(ei, ew, E);
    dinv_kernel    <<<(Nn+255)/256, 256>>>();

    // 2) GRU temporal encoder on tensor cores (warp mma.sync, bf16 hi/lo split,
    //    x/bias folded exactly into the fp32 accumulator init)
    gru_mma_kernel<<<Mn/64, 128>>>(x, w_ih, w_hh, b_ih, b_hh);

    // 3) conv1: xw1 = h@W1, out1 init = dinv^2*xw1 (self loop), then edge scatter
    mm_init_kernel<Hn, Hn, false><<<(Mn+127)/128, 128>>>(p_h, W1, nullptr, p_xw1, p_out1);
    scatter_kernel<Hn><<<((size_t)E*32 + 255)/256, 256>>>(ei, ew, p_xw1, p_out1, E);

    // 4) conv2: relu(out1+b1)@W2, self-loop init, edge scatter
    mm_init_kernel<Hn, On, true><<<(Mn+127)/128, 128>>>(p_out1, W2, b1, p_xw2, p_out2);
    scatter_kernel<On><<<((size_t)E*32 + 255)/256, 256>>>(ei, ew, p_xw2, p_out2, E);

    // 5) head: (out2+b2)@Wfc + bfc, transpose to [b][n]
    final_kernel<<<(Mn+255)/256, 256>>>(b2, Wfc, bfc, y);
}

// round 14
// speedup vs baseline: 1.2582x; 1.2582x over previous
#include <cuda_runtime.h>
#include <cuda_bf16.h>
#include <cstdint>

// Problem constants (fixed-shape problem)
#define Bn 16
#define Nn 10000
#define Tn 24
#define Hn 32
#define On 16
#define Mn (Bn*Nn)          // 160000 rows
#define G3H 96              // 3*H

// ---------------- device scratch (no allocations allowed) ----------------
__device__ float g_h   [Mn*Hn];   // GRU output, layout [n][b][32]
__device__ float g_xw1 [Mn*Hn];   // conv1 x@W1,   [n][b][32]
__device__ float g_out1[Mn*Hn];   // conv1 result, [n][b][32]
__device__ float g_xw2 [Mn*On];   // conv2 x@W2,   [n][b][16]
__device__ float g_out2[Mn*On];   // conv2 result, [n][b][16]
__device__ float g_deg [Nn];
__device__ float g_dinv[Nn];

// ---------------- helpers ----------------
__device__ __forceinline__ float tanhap(float x){
    float y;
    asm("tanh.approx.f32 %0, %1;" : "=f"(y) : "f"(x));
    return y;
}
__device__ __forceinline__ uint32_t pack_bf2(__nv_bfloat16 lo, __nv_bfloat16 hi){
    __nv_bfloat162 t = __halves2bfloat162(lo, hi);   // .x -> low 16 bits
    return *reinterpret_cast<uint32_t*>(&t);
}
// split two floats into packed bf16 hi + residual lo
__device__ __forceinline__ void split2(float a, float b, uint32_t& hi, uint32_t& lo){
    __nv_bfloat16 ah = __float2bfloat16(a), bh = __float2bfloat16(b);
    hi = pack_bf2(ah, bh);
    lo = pack_bf2(__float2bfloat16(a - __bfloat162float(ah)),
                  __float2bfloat16(b - __bfloat162float(bh)));
}
__device__ __forceinline__ void mma_bf16(float* d, const uint32_t* a, uint32_t b0, uint32_t b1){
    asm volatile("mma.sync.aligned.m16n8k16.row.col.f32.bf16.bf16.f32 "
        "{%0,%1,%2,%3}, {%4,%5,%6,%7}, {%8,%9}, {%0,%1,%2,%3};"
        : "+f"(d[0]),"+f"(d[1]),"+f"(d[2]),"+f"(d[3])
        : "r"(a[0]),"r"(a[1]),"r"(a[2]),"r"(a[3]), "r"(b0),"r"(b1));
}

// ---------------- degree / norm ----------------
__global__ void deg_init_kernel(){
    int i = blockIdx.x*blockDim.x + threadIdx.x;
    if (i < Nn) g_deg[i] = 1.f;               // self-loop weight
}
__global__ void deg_acc_kernel(const int* __restrict__ ei,
                               const float* __restrict__ ew, int E){
    int e = blockIdx.x*blockDim.x + threadIdx.x;
    if (e < E) atomicAdd(&g_deg[ei[E + e]], ew[e]);
}
__global__ void dinv_kernel(){
    int i = blockIdx.x*blockDim.x + threadIdx.x;
    if (i < Nn){
        float d = g_deg[i];
        g_dinv[i] = d > 0.f ? rsqrtf(d) : 0.f;
    }
}

// ---------------- GRU via warp-level mma.sync (bf16 hi/lo split) ----------------
// Warp = 16 sequences. Per step: D[16,96] = A[16,32] x B[32,96] via MMA with
// D PRE-INITIALIZED to the exact fp32 x/bias contribution (accumulate-in).
//   A = h(32) bf16 hi/lo; B = w_hh per gate. n-tiles: 0-3 r, 4-7 z, 8-11 nh.
//   xn = win*x + bxn computed scalar (exact), kept in registers.
// h persists in D-layout fragment registers; B frags in smem as ONE uint4 per
// (tile, ktile, lane) -> single LDS.128 per MMA group.
__device__ __forceinline__ float bval(int nt, int k, int gcol, const float* w_hh){
    int gate = nt >> 2;
    int u = (nt & 3)*8 + gcol;
    return w_hh[(gate*32 + u)*32 + k];
}

__global__ __launch_bounds__(128,3)
void gru_mma_kernel(const float* __restrict__ x,
                    const float* __restrict__ w_ih, const float* __restrict__ w_hh,
                    const float* __restrict__ b_ih, const float* __restrict__ b_hh)
{
    // B fragments: [tile][ktile][lane] = (bh_r0, bh_r1, bl_r0, bl_r1)
    __shared__ uint4 sB4[12][2][32];
    // per-unit gate constants: sc4[2u]=(wir,wiz,win,bR), sc4[2u+1]=(bZ,bhn,bxn,0)
    __shared__ float4 sc4[64];

    const int tid  = threadIdx.x;
    const int lane = tid & 31;
    const int wid  = tid >> 5;
    const int g    = lane >> 2;      // fragment group (row / B n-col)
    const int tig  = lane & 3;       // thread in group

    // ---- one-time B fragment staging (h-part only) ----
    for (int i = tid; i < 12*2*32; i += 128){
        int nt = i >> 6;             // /64
        int kt = (i >> 5) & 1;
        int ln = i & 31;
        int gg = ln >> 2, tg = ln & 3;
        uint32_t h0, l0, h1, l1;
        {   int k0 = 16*kt + 2*tg;
            split2(bval(nt, k0, gg, w_hh), bval(nt, k0+1, gg, w_hh), h0, l0); }
        {   int k0 = 16*kt + 2*tg + 8;
            split2(bval(nt, k0, gg, w_hh), bval(nt, k0+1, gg, w_hh), h1, l1); }
        sB4[nt][kt][ln] = make_uint4(h0, h1, l0, l1);
    }
    // ---- one-time gate-constant staging ----
    if (tid < 64){
        int u = tid >> 1;
        if ((tid & 1) == 0)
            sc4[tid] = make_float4(w_ih[u], w_ih[32+u], w_ih[64+u], b_ih[u] + b_hh[u]);
        else
            sc4[tid] = make_float4(b_ih[32+u] + b_hh[32+u], b_hh[64+u], b_ih[64+u], 0.f);
    }
    __syncthreads();

    const int m0 = blockIdx.x*64 + wid*16;      // 2500 blocks * 4 warps * 16 seqs
    const float* xa = x + (size_t)(m0 + g    )*Tn;
    const float* xb = x + (size_t)(m0 + g + 8)*Tn;

    // h in D-fragment layout: h[nt][e], nt=0..3 (units 8nt+2tig+{0,1}; rows g,g+8)
    float h[4][4];
#pragma unroll
    for (int a = 0; a < 4; a++)
#pragma unroll
        for (int e = 0; e < 4; e++) h[a][e] = 0.f;

#pragma unroll 1
    for (int t = 0; t < Tn; t++){
        // ---- pack A fragments (hi/lo) from h (k = 0..31 only) ----
        uint32_t Ah[2][4], Al[2][4];
#pragma unroll
        for (int kt = 0; kt < 2; kt++){
            split2(h[2*kt  ][0], h[2*kt  ][1], Ah[kt][0], Al[kt][0]);
            split2(h[2*kt  ][2], h[2*kt  ][3], Ah[kt][1], Al[kt][1]);
            split2(h[2*kt+1][0], h[2*kt+1][1], Ah[kt][2], Al[kt][2]);
            split2(h[2*kt+1][2], h[2*kt+1][3], Ah[kt][3], Al[kt][3]);
        }

        // ---- D init: exact fp32 x/bias contribution (broadcast LDS) ----
        float xga = __ldg(xa + t);
        float xgb = __ldg(xb + t);
        float D[12][4], Xn[4][4];
#pragma unroll
        for (int nt = 0; nt < 4; nt++){
#pragma unroll
            for (int eo = 0; eo < 2; eo++){
                int u = 8*nt + 2*tig + eo;
                float4 c0 = sc4[2*u];       // wir,wiz,win,bR
                float4 c1 = sc4[2*u+1];     // bZ,bhn,bxn,-
                D [nt  ][eo  ] = fmaf(c0.x, xga, c0.w);
                D [nt  ][eo+2] = fmaf(c0.x, xgb, c0.w);
                D [nt+4][eo  ] = fmaf(c0.y, xga, c1.x);
                D [nt+4][eo+2] = fmaf(c0.y, xgb, c1.x);
                D [nt+8][eo  ] = c1.y;
                D [nt+8][eo+2] = c1.y;
                Xn[nt  ][eo  ] = fmaf(c0.z, xga, c1.z);
                Xn[nt  ][eo+2] = fmaf(c0.z, xgb, c1.z);
            }
        }

        // ---- MMAs: 12 tiles x 2 k-tiles x 3 split products, accumulate into D ----
#pragma unroll
        for (int nt = 0; nt < 12; nt++){
#pragma unroll
            for (int kt = 0; kt < 2; kt++){
                uint4 bb = sB4[nt][kt][lane];     // one LDS.128
                mma_bf16(D[nt], Ah[kt], bb.x, bb.y);
                mma_bf16(D[nt], Al[kt], bb.x, bb.y);
                mma_bf16(D[nt], Ah[kt], bb.z, bb.w);
            }
        }

        // ---- gates + state update (element-wise, same fragment positions) ----
#pragma unroll
        for (int nt = 0; nt < 4; nt++)
#pragma unroll
            for (int e = 0; e < 4; e++){
                float r  = fmaf(0.5f, tanhap(0.5f*D[nt  ][e]), 0.5f);
                float z  = fmaf(0.5f, tanhap(0.5f*D[nt+4][e]), 0.5f);
                float nv = tanhap(fmaf(r, D[nt+8][e], Xn[nt][e]));
                h[nt][e] = fmaf(z, h[nt][e] - nv, nv);
            }
    }

    // ---- write final h: thread owns (rows g,g+8) x (cols 8nt+2tig,+1) ----
#pragma unroll
    for (int nt = 0; nt < 4; nt++){
        int j0 = nt*8 + 2*tig;
        {
            int m = m0 + g;
            int b = m / Nn, nn = m % Nn;
            *(float2*)(g_h + ((size_t)nn*Bn + b)*Hn + j0) = make_float2(h[nt][0], h[nt][1]);
        }
        {
            int m = m0 + g + 8;
            int b = m / Nn, nn = m % Nn;
            *(float2*)(g_h + ((size_t)nn*Bn + b)*Hn + j0) = make_float2(h[nt][2], h[nt][3]);
        }
    }
}

// ---------------- dense matmul + self-loop init (+ optional bias+relu on input) ----------------
template<int CIN, int COUT, bool RELU>
__global__ void mm_init_kernel(const float* __restrict__ in,
                               const float* __restrict__ W,
                               const float* __restrict__ bin,
                               float* __restrict__ xw,
                               float* __restrict__ outbuf)
{
    __shared__ float sW[CIN*COUT];
    __shared__ float sb[CIN];
    int tid = threadIdx.x;
    for (int i = tid; i < CIN*COUT; i += blockDim.x) sW[i] = W[i];
    if (RELU && tid < CIN) sb[tid] = bin[tid];
    __syncthreads();

    int r = blockIdx.x*blockDim.x + tid;
    if (r >= Mn) return;
    int n = r / Bn;
    float di = g_dinv[n];
    float dd = di*di;                         // self-loop norm

    float v[CIN];
#pragma unroll
    for (int i = 0; i < CIN; i += 4){
        float4 t4 = *(const float4*)(in + (size_t)r*CIN + i);
        v[i]=t4.x; v[i+1]=t4.y; v[i+2]=t4.z; v[i+3]=t4.w;
    }
    if (RELU){
#pragma unroll
        for (int i = 0; i < CIN; i++) v[i] = fmaxf(v[i] + sb[i], 0.f);
    }
    float acc[COUT];
#pragma unroll
    for (int o = 0; o < COUT; o++) acc[o] = 0.f;
#pragma unroll
    for (int i = 0; i < CIN; i++){
        float vi = v[i];
#pragma unroll
        for (int o = 0; o < COUT; o++) acc[o] += vi * sW[i*COUT + o];
    }
    float* px = xw     + (size_t)r*COUT;
    float* po = outbuf + (size_t)r*COUT;
#pragma unroll
    for (int o = 0; o < COUT; o += 4){
        *(float4*)(px+o) = make_float4(acc[o],    acc[o+1],    acc[o+2],    acc[o+3]);
        *(float4*)(po+o) = make_float4(dd*acc[o], dd*acc[o+1], dd*acc[o+2], dd*acc[o+3]);
    }
}

// ---------------- edge scatter: one warp per edge, vectorized fp32 RED ----------------
__device__ __forceinline__ void red4(float* p, float4 v){
    asm volatile("red.global.add.v4.f32 [%0], {%1, %2, %3, %4};"
                 :: "l"(p), "f"(v.x), "f"(v.y), "f"(v.z), "f"(v.w) : "memory");
}

template<int C>
__global__ void scatter_kernel(const int* __restrict__ ei,
                               const float* __restrict__ ew,
                               const float* __restrict__ xw,
                               float* __restrict__ out, int E)
{
    int g    = blockIdx.x*blockDim.x + threadIdx.x;
    int warp = g >> 5;
    int lane = g & 31;
    if (warp >= E) return;

    int src = 0, tgt = 0; float nrm = 0.f;
    if (lane == 0){
        src = ei[warp];
        tgt = ei[E + warp];
        nrm = g_dinv[src] * ew[warp] * g_dinv[tgt];
    }
    src = __shfl_sync(0xffffffffu, src, 0);
    tgt = __shfl_sync(0xffffffffu, tgt, 0);
    nrm = __shfl_sync(0xffffffffu, nrm, 0);

    const float4* s = (const float4*)(xw + (size_t)src*(Bn*C));
    float*        d = out + (size_t)tgt*(Bn*C);
#pragma unroll
    for (int i = 0; i < (Bn*C)/128; i++){
        float4 v = s[lane + 32*i];
        v.x *= nrm; v.y *= nrm; v.z *= nrm; v.w *= nrm;
        red4(d + 4*(lane + 32*i), v);
    }
}

// ---------------- final linear head + [b][n] transpose ----------------
__global__ void final_kernel(const float* __restrict__ b2,
                             const float* __restrict__ Wfc,
                             const float* __restrict__ bfc,
                             float* __restrict__ y)
{
    int r = blockIdx.x*blockDim.x + threadIdx.x;
    if (r >= Mn) return;
    int n = r / Bn, b = r % Bn;
    const float* row = g_out2 + (size_t)r*On;
    float acc = bfc[0];
#pragma unroll
    for (int o = 0; o < On; o++) acc += (row[o] + b2[o]) * Wfc[o];
    y[(size_t)b*Nn + n] = acc;
}

// ---------------- launch ----------------
extern "C" void kernel_launch(void* const* d_in, const int* in_sizes, int n_in,
                              void* d_out, int out_size)
{
    const float* x    = (const float*)d_in[0];
    const int*   ei   = (const int*)  d_in[1];
    const float* ew   = (const float*)d_in[2];
    const float* w_ih = (const float*)d_in[3];
    const float* w_hh = (const float*)d_in[4];
    const float* b_ih = (const float*)d_in[5];
    const float* b_hh = (const float*)d_in[6];
    const float* W1   = (const float*)d_in[7];
    const float* b1   = (const float*)d_in[8];
    const float* W2   = (const float*)d_in[9];
    const float* b2   = (const float*)d_in[10];
    const float* Wfc  = (const float*)d_in[11];
    const float* bfc  = (const float*)d_in[12];
    float* y = (float*)d_out;
    int E = in_sizes[2];

    // resolve __device__ scratch addresses (not an allocation)
    float *p_h, *p_xw1, *p_out1, *p_xw2, *p_out2;
    cudaGetSymbolAddress((void**)&p_h,    g_h);
    cudaGetSymbolAddress((void**)&p_xw1,  g_xw1);
    cudaGetSymbolAddress((void**)&p_out1, g_out1);
    cudaGetSymbolAddress((void**)&p_xw2,  g_xw2);
    cudaGetSymbolAddress((void**)&p_out2, g_out2);

    // 1) gcn_norm
    deg_init_kernel<<<(Nn+255)/256, 256>>>();
    deg_acc_kernel <<<(E +255)/256, 256>>>(ei, ew, E);
    dinv_kernel    <<<(Nn+255)/256, 256>>>();

    // 2) GRU temporal encoder on tensor cores (warp mma.sync, bf16 hi/lo split,
    //    x/bias folded exactly into the fp32 accumulator init)
    gru_mma_kernel<<<Mn/64, 128>>>(x, w_ih, w_hh, b_ih, b_hh);

    // 3) conv1: xw1 = h@W1, out1 init = dinv^2*xw1 (self loop), then edge scatter
    mm_init_kernel<Hn, Hn, false><<<(Mn+127)/128, 128>>>(p_h, W1, nullptr, p_xw1, p_out1);
    scatter_kernel<Hn><<<((size_t)E*32 + 255)/256, 256>>>(ei, ew, p_xw1, p_out1, E);

    // 4) conv2: relu(out1+b1)@W2, self-loop init, edge scatter
    mm_init_kernel<Hn, On, true><<<(Mn+127)/128, 128>>>(p_out1, W2, b1, p_xw2, p_out2);
    scatter_kernel<On><<<((size_t)E*32 + 255)/256, 256>>>(ei, ew, p_xw2, p_out2, E);

    // 5) head: (out2+b2)@Wfc + bfc, transpose to [b][n]
    final_kernel<<<(Mn+255)/256, 256>>>(b2, Wfc, bfc, y);
}

// round 15
// speedup vs baseline: 1.3959x; 1.1095x over previous
#include <cuda_runtime.h>
#include <cuda_bf16.h>
#include <cstdint>

// Problem constants (fixed-shape problem)
#define Bn 16
#define Nn 10000
#define Tn 24
#define Hn 32
#define On 16
#define Mn (Bn*Nn)          // 160000 rows
#define G3H 96              // 3*H

// ---------------- device scratch (no allocations allowed) ----------------
__device__ float g_xw1 [Mn*Hn];   // conv1 x@W1,   [n][b][32]
__device__ float g_out1[Mn*Hn];   // conv1 result, [n][b][32]
__device__ float g_xw2 [Mn*On];   // conv2 x@W2,   [n][b][16]
__device__ float g_out2[Mn*On];   // conv2 result, [n][b][16]
__device__ float g_deg [Nn];
__device__ float g_dinv[Nn];

// ---------------- helpers ----------------
__device__ __forceinline__ float tanhap(float x){
    float y;
    asm("tanh.approx.f32 %0, %1;" : "=f"(y) : "f"(x));
    return y;
}
__device__ __forceinline__ uint32_t pack_bf2(__nv_bfloat16 lo, __nv_bfloat16 hi){
    __nv_bfloat162 t = __halves2bfloat162(lo, hi);   // .x -> low 16 bits
    return *reinterpret_cast<uint32_t*>(&t);
}
// split two floats into packed bf16 hi + residual lo
__device__ __forceinline__ void split2(float a, float b, uint32_t& hi, uint32_t& lo){
    __nv_bfloat16 ah = __float2bfloat16(a), bh = __float2bfloat16(b);
    hi = pack_bf2(ah, bh);
    lo = pack_bf2(__float2bfloat16(a - __bfloat162float(ah)),
                  __float2bfloat16(b - __bfloat162float(bh)));
}
__device__ __forceinline__ void mma_bf16(float* d, const uint32_t* a, uint32_t b0, uint32_t b1){
    asm volatile("mma.sync.aligned.m16n8k16.row.col.f32.bf16.bf16.f32 "
        "{%0,%1,%2,%3}, {%4,%5,%6,%7}, {%8,%9}, {%0,%1,%2,%3};"
        : "+f"(d[0]),"+f"(d[1]),"+f"(d[2]),"+f"(d[3])
        : "r"(a[0]),"r"(a[1]),"r"(a[2]),"r"(a[3]), "r"(b0),"r"(b1));
}

// ---------------- degree / norm ----------------
__global__ void deg_init_kernel(){
    int i = blockIdx.x*blockDim.x + threadIdx.x;
    if (i < Nn) g_deg[i] = 1.f;               // self-loop weight
}
__global__ void deg_acc_kernel(const int* __restrict__ ei,
                               const float* __restrict__ ew, int E){
    int e = blockIdx.x*blockDim.x + threadIdx.x;
    if (e < E) atomicAdd(&g_deg[ei[E + e]], ew[e]);
}
__global__ void dinv_kernel(){
    int i = blockIdx.x*blockDim.x + threadIdx.x;
    if (i < Nn){
        float d = g_deg[i];
        g_dinv[i] = d > 0.f ? rsqrtf(d) : 0.f;
    }
}

// ---------------- GRU via warp-level mma.sync (bf16 hi/lo split) ----------------
// Hot loop identical to R12 (scalar sB loads, 146 regs, no spills).
// NEW: epilogue fuses conv1's dense matmul (xw1 = h@W1) as 24 extra MMAs and
// writes g_xw1 + self-loop-initialized g_out1 directly; g_h is eliminated.
__device__ __forceinline__ float bval(int nt, int k, int gcol, const float* w_hh){
    int gate = nt >> 2;
    int u = (nt & 3)*8 + gcol;
    return w_hh[(gate*32 + u)*32 + k];
}

__global__ __launch_bounds__(128,3)
void gru_mma_kernel(const float* __restrict__ x,
                    const float* __restrict__ w_ih, const float* __restrict__ w_hh,
                    const float* __restrict__ b_ih, const float* __restrict__ b_hh,
                    const float* __restrict__ W1)
{
    // B fragments: [tile][ktile][split][reg][lane]  (12 h-tiles, 2 k-tiles)
    __shared__ uint32_t sB[12][2][2][2][32];
    // per-unit gate constants: sc4[2u]=(wir,wiz,win,bR), sc4[2u+1]=(bZ,bhn,bxn,0)
    __shared__ float4 sc4[64];
    // W1 fragments for the fused conv1 matmul: [tile][ktile][lane]=(h0,h1,l0,l1)
    __shared__ uint4 sW1[4][2][32];

    const int tid  = threadIdx.x;
    const int lane = tid & 31;
    const int wid  = tid >> 5;
    const int g    = lane >> 2;      // fragment group (row / B n-col)
    const int tig  = lane & 3;       // thread in group

    // ---- one-time B fragment staging (h-part only) ----
    for (int i = tid; i < 12*2*2*2*32; i += 128){
        int nt  = i >> 8;            // /256
        int rem = i & 255;
        int kt  = rem >> 7;          // /128
        int r   = (rem >> 5) & 1;    // reg
        int ln  = i & 31;
        int gg = ln >> 2, tg = ln & 3;
        int k0 = 16*kt + 2*tg + 8*r;
        float v0 = bval(nt, k0,   gg, w_hh);
        float v1 = bval(nt, k0+1, gg, w_hh);
        uint32_t hi, lo;
        split2(v0, v1, hi, lo);
        sB[nt][kt][0][r][ln] = hi;
        sB[nt][kt][1][r][ln] = lo;
    }
    // ---- one-time gate-constant staging ----
    if (tid < 64){
        int u = tid >> 1;
        if ((tid & 1) == 0)
            sc4[tid] = make_float4(w_ih[u], w_ih[32+u], w_ih[64+u], b_ih[u] + b_hh[u]);
        else
            sc4[tid] = make_float4(b_ih[32+u] + b_hh[32+u], b_hh[64+u], b_ih[64+u], 0.f);
    }
    // ---- one-time W1 fragment staging (W1 stored [in=k][out=u]) ----
    for (int i = tid; i < 4*2*32; i += 128){
        int nt = i >> 6;
        int kt = (i >> 5) & 1;
        int ln = i & 31;
        int gg = ln >> 2, tg = ln & 3;
        int u  = nt*8 + gg;
        uint32_t h0, l0, h1, l1;
        {   int k0 = 16*kt + 2*tg;
            split2(W1[k0*Hn + u], W1[(k0+1)*Hn + u], h0, l0); }
        {   int k0 = 16*kt + 2*tg + 8;
            split2(W1[k0*Hn + u], W1[(k0+1)*Hn + u], h1, l1); }
        sW1[nt][kt][ln] = make_uint4(h0, h1, l0, l1);
    }
    __syncthreads();

    const int m0 = blockIdx.x*64 + wid*16;      // 2500 blocks * 4 warps * 16 seqs
    const float* xa = x + (size_t)(m0 + g    )*Tn;
    const float* xb = x + (size_t)(m0 + g + 8)*Tn;

    // h in D-fragment layout: h[nt][e], nt=0..3 (units 8nt+2tig+{0,1}; rows g,g+8)
    float h[4][4];
#pragma unroll
    for (int a = 0; a < 4; a++)
#pragma unroll
        for (int e = 0; e < 4; e++) h[a][e] = 0.f;

#pragma unroll 1
    for (int t = 0; t < Tn; t++){
        // ---- pack A fragments (hi/lo) from h (k = 0..31 only) ----
        uint32_t Ah[2][4], Al[2][4];
#pragma unroll
        for (int kt = 0; kt < 2; kt++){
            split2(h[2*kt  ][0], h[2*kt  ][1], Ah[kt][0], Al[kt][0]);
            split2(h[2*kt  ][2], h[2*kt  ][3], Ah[kt][1], Al[kt][1]);
            split2(h[2*kt+1][0], h[2*kt+1][1], Ah[kt][2], Al[kt][2]);
            split2(h[2*kt+1][2], h[2*kt+1][3], Ah[kt][3], Al[kt][3]);
        }

        // ---- D init: exact fp32 x/bias contribution (broadcast LDS) ----
        float xga = __ldg(xa + t);
        float xgb = __ldg(xb + t);
        float D[12][4], Xn[4][4];
#pragma unroll
        for (int nt = 0; nt < 4; nt++){
#pragma unroll
            for (int eo = 0; eo < 2; eo++){
                int u = 8*nt + 2*tig + eo;
                float4 c0 = sc4[2*u];       // wir,wiz,win,bR
                float4 c1 = sc4[2*u+1];     // bZ,bhn,bxn,-
                D [nt  ][eo  ] = fmaf(c0.x, xga, c0.w);
                D [nt  ][eo+2] = fmaf(c0.x, xgb, c0.w);
                D [nt+4][eo  ] = fmaf(c0.y, xga, c1.x);
                D [nt+4][eo+2] = fmaf(c0.y, xgb, c1.x);
                D [nt+8][eo  ] = c1.y;
                D [nt+8][eo+2] = c1.y;
                Xn[nt  ][eo  ] = fmaf(c0.z, xga, c1.z);
                Xn[nt  ][eo+2] = fmaf(c0.z, xgb, c1.z);
            }
        }

        // ---- MMAs: 12 tiles x 2 k-tiles x 3 split products, accumulate into D ----
#pragma unroll
        for (int nt = 0; nt < 12; nt++){
#pragma unroll
            for (int kt = 0; kt < 2; kt++){
                uint32_t bh0 = sB[nt][kt][0][0][lane], bh1 = sB[nt][kt][0][1][lane];
                uint32_t bl0 = sB[nt][kt][1][0][lane], bl1 = sB[nt][kt][1][1][lane];
                mma_bf16(D[nt], Ah[kt], bh0, bh1);
                mma_bf16(D[nt], Al[kt], bh0, bh1);
                mma_bf16(D[nt], Ah[kt], bl0, bl1);
            }
        }

        // ---- gates + state update (element-wise, same fragment positions) ----
#pragma unroll
        for (int nt = 0; nt < 4; nt++)
#pragma unroll
            for (int e = 0; e < 4; e++){
                float r  = fmaf(0.5f, tanhap(0.5f*D[nt  ][e]), 0.5f);
                float z  = fmaf(0.5f, tanhap(0.5f*D[nt+4][e]), 0.5f);
                float nv = tanhap(fmaf(r, D[nt+8][e], Xn[nt][e]));
                h[nt][e] = fmaf(z, h[nt][e] - nv, nv);
            }
    }

    // ======== fused conv1 dense matmul: xw1 = h @ W1 (once per warp) ========
    {
        uint32_t Ah[2][4], Al[2][4];
#pragma unroll
        for (int kt = 0; kt < 2; kt++){
            split2(h[2*kt  ][0], h[2*kt  ][1], Ah[kt][0], Al[kt][0]);
            split2(h[2*kt  ][2], h[2*kt  ][3], Ah[kt][1], Al[kt][1]);
            split2(h[2*kt+1][0], h[2*kt+1][1], Ah[kt][2], Al[kt][2]);
            split2(h[2*kt+1][2], h[2*kt+1][3], Ah[kt][3], Al[kt][3]);
        }
        float Dx[4][4];
#pragma unroll
        for (int nt = 0; nt < 4; nt++){
#pragma unroll
            for (int e = 0; e < 4; e++) Dx[nt][e] = 0.f;
#pragma unroll
            for (int kt = 0; kt < 2; kt++){
                uint4 bb = sW1[nt][kt][lane];
                mma_bf16(Dx[nt], Ah[kt], bb.x, bb.y);
                mma_bf16(Dx[nt], Al[kt], bb.x, bb.y);
                mma_bf16(Dx[nt], Ah[kt], bb.z, bb.w);
            }
        }
        // self-loop norms for the two rows this thread owns
        int mA = m0 + g,      nnA = mA % Nn, bA = mA / Nn;
        int mB = m0 + g + 8,  nnB = mB % Nn, bB = mB / Nn;
        float diA = g_dinv[nnA], ddA = diA*diA;
        float diB = g_dinv[nnB], ddB = diB*diB;
        float* xwA = g_xw1  + ((size_t)nnA*Bn + bA)*Hn;
        float* xwB = g_xw1  + ((size_t)nnB*Bn + bB)*Hn;
        float* o1A = g_out1 + ((size_t)nnA*Bn + bA)*Hn;
        float* o1B = g_out1 + ((size_t)nnB*Bn + bB)*Hn;
#pragma unroll
        for (int nt = 0; nt < 4; nt++){
            int j0 = nt*8 + 2*tig;
            *(float2*)(xwA + j0) = make_float2(Dx[nt][0], Dx[nt][1]);
            *(float2*)(xwB + j0) = make_float2(Dx[nt][2], Dx[nt][3]);
            *(float2*)(o1A + j0) = make_float2(ddA*Dx[nt][0], ddA*Dx[nt][1]);
            *(float2*)(o1B + j0) = make_float2(ddB*Dx[nt][2], ddB*Dx[nt][3]);
        }
    }
}

// ---------------- dense matmul + self-loop init (+ optional bias+relu on input) ----------------
template<int CIN, int COUT, bool RELU>
__global__ void mm_init_kernel(const float* __restrict__ in,
                               const float* __restrict__ W,
                               const float* __restrict__ bin,
                               float* __restrict__ xw,
                               float* __restrict__ outbuf)
{
    __shared__ float sW[CIN*COUT];
    __shared__ float sb[CIN];
    int tid = threadIdx.x;
    for (int i = tid; i < CIN*COUT; i += blockDim.x) sW[i] = W[i];
    if (RELU && tid < CIN) sb[tid] = bin[tid];
    __syncthreads();

    int r = blockIdx.x*blockDim.x + tid;
    if (r >= Mn) return;
    int n = r / Bn;
    float di = g_dinv[n];
    float dd = di*di;                         // self-loop norm

    float v[CIN];
#pragma unroll
    for (int i = 0; i < CIN; i += 4){
        float4 t4 = *(const float4*)(in + (size_t)r*CIN + i);
        v[i]=t4.x; v[i+1]=t4.y; v[i+2]=t4.z; v[i+3]=t4.w;
    }
    if (RELU){
#pragma unroll
        for (int i = 0; i < CIN; i++) v[i] = fmaxf(v[i] + sb[i], 0.f);
    }
    float acc[COUT];
#pragma unroll
    for (int o = 0; o < COUT; o++) acc[o] = 0.f;
#pragma unroll
    for (int i = 0; i < CIN; i++){
        float vi = v[i];
#pragma unroll
        for (int o = 0; o < COUT; o++) acc[o] += vi * sW[i*COUT + o];
    }
    float* px = xw     + (size_t)r*COUT;
    float* po = outbuf + (size_t)r*COUT;
#pragma unroll
    for (int o = 0; o < COUT; o += 4){
        *(float4*)(px+o) = make_float4(acc[o],    acc[o+1],    acc[o+2],    acc[o+3]);
        *(float4*)(po+o) = make_float4(dd*acc[o], dd*acc[o+1], dd*acc[o+2], dd*acc[o+3]);
    }
}

// ---------------- edge scatter: one warp per edge, vectorized fp32 RED ----------------
__device__ __forceinline__ void red4(float* p, float4 v){
    asm volatile("red.global.add.v4.f32 [%0], {%1, %2, %3, %4};"
                 :: "l"(p), "f"(v.x), "f"(v.y), "f"(v.z), "f"(v.w) : "memory");
}

template<int C>
__global__ void scatter_kernel(const int* __restrict__ ei,
                               const float* __restrict__ ew,
                               const float* __restrict__ xw,
                               float* __restrict__ out, int E)
{
    int g    = blockIdx.x*blockDim.x + threadIdx.x;
    int warp = g >> 5;
    int lane = g & 31;
    if (warp >= E) return;

    int src = 0, tgt = 0; float nrm = 0.f;
    if (lane == 0){
        src = ei[warp];
        tgt = ei[E + warp];
        nrm = g_dinv[src] * ew[warp] * g_dinv[tgt];
    }
    src = __shfl_sync(0xffffffffu, src, 0);
    tgt = __shfl_sync(0xffffffffu, tgt, 0);
    nrm = __shfl_sync(0xffffffffu, nrm, 0);

    const float4* s = (const float4*)(xw + (size_t)src*(Bn*C));
    float*        d = out + (size_t)tgt*(Bn*C);
#pragma unroll
    for (int i = 0; i < (Bn*C)/128; i++){
        float4 v = s[lane + 32*i];
        v.x *= nrm; v.y *= nrm; v.z *= nrm; v.w *= nrm;
        red4(d + 4*(lane + 32*i), v);
    }
}

// ---------------- final linear head + [b][n] transpose ----------------
__global__ void final_kernel(const float* __restrict__ b2,
                             const float* __restrict__ Wfc,
                             const float* __restrict__ bfc,
                             float* __restrict__ y)
{
    int r = blockIdx.x*blockDim.x + threadIdx.x;
    if (r >= Mn) return;
    int n = r / Bn, b = r % Bn;
    const float* row = g_out2 + (size_t)r*On;
    float acc = bfc[0];
#pragma unroll
    for (int o = 0; o < On; o++) acc += (row[o] + b2[o]) * Wfc[o];
    y[(size_t)b*Nn + n] = acc;
}

// ---------------- launch ----------------
extern "C" void kernel_launch(void* const* d_in, const int* in_sizes, int n_in,
                              void* d_out, int out_size)
{
    const float* x    = (const float*)d_in[0];
    const int*   ei   = (const int*)  d_in[1];
    const float* ew   = (const float*)d_in[2];
    const float* w_ih = (const float*)d_in[3];
    const float* w_hh = (const float*)d_in[4];
    const float* b_ih = (const float*)d_in[5];
    const float* b_hh = (const float*)d_in[6];
    const float* W1   = (const float*)d_in[7];
    const float* b1   = (const float*)d_in[8];
    const float* W2   = (const float*)d_in[9];
    const float* b2   = (const float*)d_in[10];
    const float* Wfc  = (const float*)d_in[11];
    const float* bfc  = (const float*)d_in[12];
    float* y = (float*)d_out;
    int E = in_sizes[2];

    // resolve __device__ scratch addresses (not an allocation)
    float *p_xw1, *p_out1, *p_xw2, *p_out2;
    cudaGetSymbolAddress((void**)&p_xw1,  g_xw1);
    cudaGetSymbolAddress((void**)&p_out1, g_out1);
    cudaGetSymbolAddress((void**)&p_xw2,  g_xw2);
    cudaGetSymbolAddress((void**)&p_out2, g_out2);

    // 1) gcn_norm (must precede gru: its epilogue consumes g_dinv)
    deg_init_kernel<<<(Nn+255)/256, 256>>>();
    deg_acc_kernel <<<(E +255)/256, 256>>>(ei, ew, E);
    dinv_kernel    <<<(Nn+255)/256, 256>>>();

    // 2) GRU temporal encoder + fused conv1 matmul (xw1, out1 self-loop init)
    gru_mma_kernel<<<Mn/64, 128>>>(x, w_ih, w_hh, b_ih, b_hh, W1);

    // 3) conv1 edge scatter
    scatter_kernel<Hn><<<((size_t)E*32 + 255)/256, 256>>>(ei, ew, p_xw1, p_out1, E);

    // 4) conv2: relu(out1+b1)@W2, self-loop init, edge scatter
    mm_init_kernel<Hn, On, true><<<(Mn+127)/128, 128>>>(p_out1, W2, b1, p_xw2, p_out2);
    scatter_kernel<On><<<((size_t)E*32 + 255)/256, 256>>>(ei, ew, p_xw2, p_out2, E);

    // 5) head: (out2+b2)@Wfc + bfc, transpose to [b][n]
    final_kernel<<<(Mn+255)/256, 256>>>(b2, Wfc, bfc, y);
}